// round 9
// baseline (speedup 1.0000x reference)
#include <cuda_runtime.h>
#include <cuda_fp16.h>
#include <cstdint>

#define NV 50000
#define NE 1250000
#define DD 64

// ---------------- scratch (device globals: no runtime allocation allowed) ----
__device__ float  g_h[(size_t)NV * DD];        // node projection h = nf@Wn + bn
__device__ __half g_msg[(size_t)NE * DD];      // messages, dst-sorted (CSR) order
__device__ int    g_rank[NE];                  // rank of edge within its dst bucket
__device__ int    g_cnt[NV];                   // histogram (zero at entry; re-zeroed last)
__device__ int    g_off[NV + 1];               // CSR offsets

// ---------------- helpers ---------------------------------------------------
__device__ __forceinline__ float sspf(float x) {
    // shifted softplus via fast-math MUFU: log(1+e^x) - log(2)
    return fmaxf(x, 0.f) + __logf(1.f + __expf(-fabsf(x))) - 0.69314718055994531f;
}

// fp16 mma m16n8k16, fp32 accumulate
__device__ __forceinline__ void mma_f16(float c[4], unsigned a0, unsigned a1,
                                        unsigned a2, unsigned a3,
                                        unsigned b0, unsigned b1) {
    asm("mma.sync.aligned.m16n8k16.row.col.f32.f16.f16.f32 "
        "{%0,%1,%2,%3}, {%4,%5,%6,%7}, {%8,%9}, {%0,%1,%2,%3};"
        : "+f"(c[0]), "+f"(c[1]), "+f"(c[2]), "+f"(c[3])
        : "r"(a0), "r"(a1), "r"(a2), "r"(a3), "r"(b0), "r"(b1));
}

__device__ __forceinline__ void ldsm4(unsigned& a0, unsigned& a1, unsigned& a2,
                                      unsigned& a3, uint32_t addr) {
    asm volatile("ldmatrix.sync.aligned.m8n8.x4.shared.b16 {%0,%1,%2,%3}, [%4];"
                 : "=r"(a0), "=r"(a1), "=r"(a2), "=r"(a3) : "r"(addr));
}

// Pack 64x64 row-major W into per-lane m16n8k16 B-fragment order (fp16).
__device__ __forceinline__ void packW(const float* __restrict__ W, unsigned* Wp,
                                      int tid, int nthr) {
    for (int idx = tid; idx < 2048; idx += nthr) {
        int j    = idx & 1;
        int lane = (idx >> 1) & 31;
        int nt   = (idx >> 6) & 7;
        int ks   = idx >> 9;                  // 0..3
        int g = lane >> 2, t4 = lane & 3;
        int kb = ks * 16 + t4 * 2 + j * 8;
        int n  = nt * 8 + g;
        __half2 v = __floats2half2_rn(W[kb * DD + n], W[(kb + 1) * DD + n]);
        Wp[idx] = *(unsigned*)&v;
    }
}

// block-level [128,64]@[64,64] (h_kernel): A via manual LDS
__device__ __forceinline__ void gemm_tile(const __half (*As)[72],
                                          const unsigned* __restrict__ Wp,
                                          float acc[8][4], int wr, int gid,
                                          int tig, int lane) {
    #pragma unroll
    for (int ks = 0; ks < 4; ks++) {
        int k0 = ks * 16 + tig * 2;
        unsigned a0 = *(const unsigned*)&As[wr + gid    ][k0];
        unsigned a1 = *(const unsigned*)&As[wr + gid + 8][k0];
        unsigned a2 = *(const unsigned*)&As[wr + gid    ][k0 + 8];
        unsigned a3 = *(const unsigned*)&As[wr + gid + 8][k0 + 8];
        #pragma unroll
        for (int nt = 0; nt < 8; nt++) {
            uint2 b = ((const uint2*)Wp)[(ks * 8 + nt) * 32 + lane];
            mma_f16(acc[nt], a0, a1, a2, a3, b.x, b.y);
        }
    }
}

// warp-level [16,64]@[64,64]: A via ldmatrix from this warp's private rows
__device__ __forceinline__ void gemm_warp(uint32_t aAddr,  // lane's LDSM base addr
                                          const unsigned* __restrict__ Wp,
                                          float acc[8][4], int lane) {
    #pragma unroll
    for (int ks = 0; ks < 4; ks++) {
        unsigned a0, a1, a2, a3;
        ldsm4(a0, a1, a2, a3, aAddr + ks * 32);  // +16 halves per k-step
        #pragma unroll
        for (int nt = 0; nt < 8; nt++) {
            uint2 b = ((const uint2*)Wp)[(ks * 8 + nt) * 32 + lane];
            mma_f16(acc[nt], a0, a1, a2, a3, b.x, b.y);
        }
    }
}

// ---------------- CSR build -------------------------------------------------
__global__ void hist_kernel(const int* __restrict__ dst) {
    int e = blockIdx.x * blockDim.x + threadIdx.x;
    if (e < NE) g_rank[e] = atomicAdd(&g_cnt[dst[e]], 1);
}

__global__ void scan_all_kernel() {  // single-block exclusive scan
    __shared__ int ws[32];
    __shared__ int tshare;
    int t = threadIdx.x, lane = t & 31, wid = t >> 5;
    int carry = 0;
    const int nchunks = (NV + 1023) / 1024;
    for (int c = 0; c < nchunks; c++) {
        int i = c * 1024 + t;
        int x = (i < NV) ? g_cnt[i] : 0;
        int incl = x;
        #pragma unroll
        for (int o = 1; o < 32; o <<= 1) {
            int n = __shfl_up_sync(0xffffffffu, incl, o);
            if (lane >= o) incl += n;
        }
        if (lane == 31) ws[wid] = incl;
        __syncthreads();
        if (t < 32) {
            int v = ws[t];
            int iv = v;
            #pragma unroll
            for (int o = 1; o < 32; o <<= 1) {
                int n = __shfl_up_sync(0xffffffffu, iv, o);
                if (t >= o) iv += n;
            }
            ws[t] = iv - v;
        }
        __syncthreads();
        int excl = ws[wid] + incl - x;
        if (i < NV) g_off[i] = carry + excl;
        if (t == 1023) tshare = excl + x;
        __syncthreads();
        carry += tshare;
        __syncthreads();
    }
    if (t == 0) g_off[NV] = NE;
}

__global__ void zero_cnt_kernel() {  // runs LAST
    int i = blockIdx.x * blockDim.x + threadIdx.x;
    if (i < NV) g_cnt[i] = 0;
}

// ---------------- h = node_feats @ Wn + bn ----------------------------------
struct HSmem {
    __half As[128][72];
    unsigned Wp[2048];
    float bs[64];
};
__global__ void __launch_bounds__(256, 2)
h_kernel(const float* __restrict__ nf, const float* __restrict__ Wn,
         const float* __restrict__ bn) {
    extern __shared__ char smraw[];
    HSmem& sm = *reinterpret_cast<HSmem*>(smraw);
    int tid = threadIdx.x, lane = tid & 31, warp = tid >> 5;
    int gid = lane >> 2, tig = lane & 3, wr = warp * 16;
    packW(Wn, sm.Wp, tid, 256);
    if (tid < 64) sm.bs[tid] = bn[tid];
    int base = blockIdx.x * 128;
    int rows = min(128, NV - base);
    #pragma unroll
    for (int j = 0; j < 8; j++) {
        int f4 = tid + j * 256;
        int r = f4 >> 4, c4 = f4 & 15;
        float4 v = (r < rows) ? ((const float4*)(nf + (size_t)(base + r) * DD))[c4]
                              : make_float4(0.f, 0.f, 0.f, 0.f);
        __half2 h0 = __floats2half2_rn(v.x, v.y);
        __half2 h1 = __floats2half2_rn(v.z, v.w);
        *(uint2*)&sm.As[r][c4 * 4] = make_uint2(*(unsigned*)&h0, *(unsigned*)&h1);
    }
    __syncthreads();
    float acc[8][4];
    #pragma unroll
    for (int i = 0; i < 8; i++)
        #pragma unroll
        for (int j = 0; j < 4; j++) acc[i][j] = 0.f;
    gemm_tile(sm.As, sm.Wp, acc, wr, gid, tig, lane);
    #pragma unroll
    for (int nt = 0; nt < 8; nt++) {
        int c0 = nt * 8 + tig * 2;
        float b0 = sm.bs[c0], b1 = sm.bs[c0 + 1];
        int r0 = wr + gid, r1 = wr + gid + 8;
        if (r0 < rows)
            *(float2*)(g_h + (size_t)(base + r0) * DD + c0) =
                make_float2(acc[nt][0] + b0, acc[nt][1] + b1);
        if (r1 < rows)
            *(float2*)(g_h + (size_t)(base + r1) * DD + c0) =
                make_float2(acc[nt][2] + b0, acc[nt][3] + b1);
    }
}

// ---------------- edge kernel: warp-independent 16-row pipelines ------------
struct EdgeSmem {
    __half As[128][72];    // 16 rows per warp: tile / intermediate / msg staging
    unsigned Wp1[2048];
    unsigned Wp2[2048];
    float b1s[64], b2s[64];
};
__global__ void __launch_bounds__(256, 3)
edge_kernel(const float* __restrict__ ef, const int* __restrict__ src,
            const int* __restrict__ dst, const float* __restrict__ We1,
            const float* __restrict__ be1, const float* __restrict__ We2,
            const float* __restrict__ be2) {
    extern __shared__ char smraw[];
    EdgeSmem& sm = *reinterpret_cast<EdgeSmem*>(smraw);
    const int tid = threadIdx.x, lane = tid & 31, warp = tid >> 5;
    const int gid = lane >> 2, tig = lane & 3;
    const int wr = warp * 16;               // this warp's first smem row

    packW(We1, sm.Wp1, tid, 256);
    packW(We2, sm.Wp2, tid, 256);
    if (tid < 64) { sm.b1s[tid] = be1[tid]; sm.b2s[tid] = be2[tid]; }
    __syncthreads();  // Wp/bias ready; no block barriers after this point

    // lane's ldmatrix base address into its warp's 16 rows
    const int row_l = (lane & 7) + ((lane >> 3) & 1) * 8;
    const int col_l = (lane >> 4) * 8;  // halves
    const uint32_t aAddr =
        (uint32_t)__cvta_generic_to_shared(&sm.As[wr + row_l][col_l]);
    // ef-load addressing: 2 lanes per row, 8 float4 each
    const int ldRow = lane >> 1, ldHalf = lane & 1;

    const int gw = blockIdx.x * 8 + warp;       // global warp id
    const int nw = gridDim.x * 8;
    const int numT = NE / 16;                   // 78125 exactly

    for (int t16 = gw; t16 < numT; t16 += nw) {
        const int base = t16 * 16;

        // per-lane metadata (rows 0..15 in lanes 0..15)
        int slotreg = 0, srcreg = 0;
        if (lane < 16) {
            slotreg = g_off[dst[base + lane]] + g_rank[base + lane];
            srcreg  = src[base + lane];
        }

        // load 16x64 ef tile -> fp16 smem (warp-private rows)
        {
            const float4* efp =
                (const float4*)(ef + (size_t)(base + ldRow) * DD) + ldHalf * 8;
            __half* dstRow = &sm.As[wr + ldRow][ldHalf * 32];
            #pragma unroll
            for (int j = 0; j < 8; j++) {
                float4 v = efp[j];
                __half2 h0 = __floats2half2_rn(v.x, v.y);
                __half2 h1 = __floats2half2_rn(v.z, v.w);
                *(uint2*)&dstRow[j * 4] = make_uint2(*(unsigned*)&h0, *(unsigned*)&h1);
            }
        }
        __syncwarp();

        float acc[8][4];
        #pragma unroll
        for (int i = 0; i < 8; i++)
            #pragma unroll
            for (int j = 0; j < 4; j++) acc[i][j] = 0.f;
        gemm_warp(aAddr, sm.Wp1, acc, lane);

        // ssp(x + b1) -> back into own rows (fp16)
        #pragma unroll
        for (int nt = 0; nt < 8; nt++) {
            int c0 = nt * 8 + tig * 2;
            float b0 = sm.b1s[c0], b1 = sm.b1s[c0 + 1];
            __half2 v0 = __floats2half2_rn(sspf(acc[nt][0] + b0), sspf(acc[nt][1] + b1));
            __half2 v1 = __floats2half2_rn(sspf(acc[nt][2] + b0), sspf(acc[nt][3] + b1));
            *(__half2*)&sm.As[wr + gid    ][c0] = v0;
            *(__half2*)&sm.As[wr + gid + 8][c0] = v1;
        }
        __syncwarp();

        // h[src] gather for this thread's two rows (overlaps with gemm2 below)
        int s0 = __shfl_sync(0xffffffffu, srcreg, gid);
        int s1 = __shfl_sync(0xffffffffu, srcreg, gid + 8);
        const float2* h0p = (const float2*)(g_h + (size_t)s0 * DD);
        const float2* h1p = (const float2*)(g_h + (size_t)s1 * DD);
        float2 hv0[8], hv1[8];
        #pragma unroll
        for (int nt = 0; nt < 8; nt++) {
            hv0[nt] = h0p[nt * 4 + tig];
            hv1[nt] = h1p[nt * 4 + tig];
        }

        #pragma unroll
        for (int i = 0; i < 8; i++)
            #pragma unroll
            for (int j = 0; j < 4; j++) acc[i][j] = 0.f;
        gemm_warp(aAddr, sm.Wp2, acc, lane);

        // msg = ssp(x + b2) * h -> fp16 staging in own rows
        #pragma unroll
        for (int nt = 0; nt < 8; nt++) {
            int c0 = nt * 8 + tig * 2;
            float b0 = sm.b2s[c0], b1 = sm.b2s[c0 + 1];
            float m0 = sspf(acc[nt][0] + b0) * hv0[nt].x;
            float m1 = sspf(acc[nt][1] + b1) * hv0[nt].y;
            float m2 = sspf(acc[nt][2] + b0) * hv1[nt].x;
            float m3 = sspf(acc[nt][3] + b1) * hv1[nt].y;
            *(__half2*)&sm.As[wr + gid    ][c0] = __floats2half2_rn(m0, m1);
            *(__half2*)&sm.As[wr + gid + 8][c0] = __floats2half2_rn(m2, m3);
        }
        __syncwarp();

        // coalesced scatter: 2 lanes per row, 64B each, slot via shuffle
        {
            int slot = __shfl_sync(0xffffffffu, slotreg, ldRow);
            const uint4* sp = (const uint4*)&sm.As[wr + ldRow][ldHalf * 32];
            uint4* dp = (uint4*)(g_msg + (size_t)slot * DD + ldHalf * 32);
            #pragma unroll
            for (int i = 0; i < 4; i++) dp[i] = sp[i];
        }
        __syncwarp();
    }
}

// ---------------- node kernel: segment-sum + ssp(agg@Wc+bc)@Wo+bo -----------
struct NodeSmem {
    float Wc[64][64];
    float Wo[64][64];
    float agg[16][64];
    float bcs[64], bos[64];
};
__global__ void __launch_bounds__(512, 2)
node_kernel(const float* __restrict__ Wc, const float* __restrict__ bc,
            const float* __restrict__ Wo, const float* __restrict__ bo,
            float* __restrict__ out) {
    extern __shared__ char smraw[];
    NodeSmem& sm = *reinterpret_cast<NodeSmem*>(smraw);
    int tid = threadIdx.x, lane = tid & 31, warp = tid >> 5;  // 16 warps
    for (int i = tid; i < 4096; i += 512) ((float*)sm.Wc)[i] = Wc[i];
    for (int i = tid; i < 4096; i += 512) ((float*)sm.Wo)[i] = Wo[i];
    if (tid < 64) { sm.bcs[tid] = bc[tid]; sm.bos[tid] = bo[tid]; }
    __syncthreads();

    int v = blockIdx.x * 16 + warp;  // NV = 3125*16 exactly
    int s0 = g_off[v], s1 = g_off[v + 1];
    float a0 = 0.f, a1 = 0.f;
    const unsigned* mp = (const unsigned*)g_msg;
    #pragma unroll 4
    for (int s = s0; s < s1; s++) {
        unsigned u = mp[(size_t)s * 32 + lane];  // 128B coalesced per warp
        float2 f = __half22float2(*(__half2*)&u);
        a0 += f.x;
        a1 += f.y;
    }
    sm.agg[warp][2 * lane]     = a0;
    sm.agg[warp][2 * lane + 1] = a1;
    __syncwarp();

    float o0 = sm.bcs[2 * lane], o1 = sm.bcs[2 * lane + 1];
    #pragma unroll 8
    for (int k = 0; k < 64; k++) {
        float av = sm.agg[warp][k];
        float2 w = *(const float2*)&sm.Wc[k][2 * lane];
        o0 += av * w.x;
        o1 += av * w.y;
    }
    o0 = sspf(o0);
    o1 = sspf(o1);
    __syncwarp();
    sm.agg[warp][2 * lane]     = o0;
    sm.agg[warp][2 * lane + 1] = o1;
    __syncwarp();

    float r0 = sm.bos[2 * lane], r1 = sm.bos[2 * lane + 1];
    #pragma unroll 8
    for (int k = 0; k < 64; k++) {
        float tv = sm.agg[warp][k];
        float2 w = *(const float2*)&sm.Wo[k][2 * lane];
        r0 += tv * w.x;
        r1 += tv * w.y;
    }
    *(float2*)(out + (size_t)v * DD + 2 * lane) = make_float2(r0, r1);
}

// ---------------- launch ----------------------------------------------------
extern "C" void kernel_launch(void* const* d_in, const int* in_sizes, int n_in,
                              void* d_out, int out_size) {
    const float* nf  = (const float*)d_in[0];
    const float* ef  = (const float*)d_in[1];
    const int*   src = (const int*)d_in[2];
    const int*   dst = (const int*)d_in[3];
    const float* We1 = (const float*)d_in[4];
    const float* be1 = (const float*)d_in[5];
    const float* We2 = (const float*)d_in[6];
    const float* be2 = (const float*)d_in[7];
    const float* Wn  = (const float*)d_in[8];
    const float* bn  = (const float*)d_in[9];
    const float* Wc  = (const float*)d_in[10];
    const float* bc  = (const float*)d_in[11];
    const float* Wo  = (const float*)d_in[12];
    const float* bo  = (const float*)d_in[13];
    float* out = (float*)d_out;

    cudaFuncSetAttribute(edge_kernel, cudaFuncAttributeMaxDynamicSharedMemorySize,
                         (int)sizeof(EdgeSmem));
    cudaFuncSetAttribute(h_kernel, cudaFuncAttributeMaxDynamicSharedMemorySize,
                         (int)sizeof(HSmem));
    cudaFuncSetAttribute(node_kernel, cudaFuncAttributeMaxDynamicSharedMemorySize,
                         (int)sizeof(NodeSmem));

    hist_kernel<<<(NE + 255) / 256, 256>>>(dst);
    scan_all_kernel<<<1, 1024>>>();
    h_kernel<<<(NV + 127) / 128, 256, sizeof(HSmem)>>>(nf, Wn, bn);
    edge_kernel<<<444, 256, sizeof(EdgeSmem)>>>(ef, src, dst, We1, be1, We2, be2);
    node_kernel<<<NV / 16, 512, sizeof(NodeSmem)>>>(Wc, bc, Wo, bo, out);
    zero_cnt_kernel<<<(NV + 1023) / 1024, 1024>>>();
}

// round 10
// speedup vs baseline: 1.0121x; 1.0121x over previous
#include <cuda_runtime.h>
#include <cuda_fp16.h>
#include <cstdint>

#define NV 50000
#define NE 1250000
#define DD 64

// ---------------- scratch (device globals: no runtime allocation allowed) ----
__device__ float  g_h[(size_t)NV * DD];        // node projection h = nf@Wn + bn
__device__ __half g_msg[(size_t)NE * DD];      // messages, dst-sorted (CSR) order
__device__ int    g_rank[NE];                  // rank of edge within its dst bucket
__device__ int    g_cnt[NV];                   // histogram (zero at entry; re-zeroed last)
__device__ int    g_off[NV + 1];               // CSR offsets

// ---------------- helpers ---------------------------------------------------
__device__ __forceinline__ float sspf(float x) {
    // shifted softplus via fast-math MUFU: log(1+e^x) - log(2)
    return fmaxf(x, 0.f) + __logf(1.f + __expf(-fabsf(x))) - 0.69314718055994531f;
}

// fp16 mma m16n8k16, fp32 accumulate
__device__ __forceinline__ void mma_f16(float c[4], unsigned a0, unsigned a1,
                                        unsigned a2, unsigned a3,
                                        unsigned b0, unsigned b1) {
    asm("mma.sync.aligned.m16n8k16.row.col.f32.f16.f16.f32 "
        "{%0,%1,%2,%3}, {%4,%5,%6,%7}, {%8,%9}, {%0,%1,%2,%3};"
        : "+f"(c[0]), "+f"(c[1]), "+f"(c[2]), "+f"(c[3])
        : "r"(a0), "r"(a1), "r"(a2), "r"(a3), "r"(b0), "r"(b1));
}

__device__ __forceinline__ void ldsm4(unsigned& a0, unsigned& a1, unsigned& a2,
                                      unsigned& a3, uint32_t addr) {
    asm volatile("ldmatrix.sync.aligned.m8n8.x4.shared.b16 {%0,%1,%2,%3}, [%4];"
                 : "=r"(a0), "=r"(a1), "=r"(a2), "=r"(a3) : "r"(addr));
}

// Pack 64x64 row-major W into per-lane m16n8k16 B-fragment order (fp16).
__device__ __forceinline__ void packW(const float* __restrict__ W, unsigned* Wp,
                                      int tid, int nthr) {
    for (int idx = tid; idx < 2048; idx += nthr) {
        int j    = idx & 1;
        int lane = (idx >> 1) & 31;
        int nt   = (idx >> 6) & 7;
        int ks   = idx >> 9;                  // 0..3
        int g = lane >> 2, t4 = lane & 3;
        int kb = ks * 16 + t4 * 2 + j * 8;
        int n  = nt * 8 + g;
        __half2 v = __floats2half2_rn(W[kb * DD + n], W[(kb + 1) * DD + n]);
        Wp[idx] = *(unsigned*)&v;
    }
}

// block-level [128,64]@[64,64] (h_kernel): A via manual LDS
__device__ __forceinline__ void gemm_tile(const __half (*As)[72],
                                          const unsigned* __restrict__ Wp,
                                          float acc[8][4], int wr, int gid,
                                          int tig, int lane) {
    #pragma unroll
    for (int ks = 0; ks < 4; ks++) {
        int k0 = ks * 16 + tig * 2;
        unsigned a0 = *(const unsigned*)&As[wr + gid    ][k0];
        unsigned a1 = *(const unsigned*)&As[wr + gid + 8][k0];
        unsigned a2 = *(const unsigned*)&As[wr + gid    ][k0 + 8];
        unsigned a3 = *(const unsigned*)&As[wr + gid + 8][k0 + 8];
        #pragma unroll
        for (int nt = 0; nt < 8; nt++) {
            uint2 b = ((const uint2*)Wp)[(ks * 8 + nt) * 32 + lane];
            mma_f16(acc[nt], a0, a1, a2, a3, b.x, b.y);
        }
    }
}

// ---------------- CSR build -------------------------------------------------
__global__ void hist_kernel(const int* __restrict__ dst) {
    int e = blockIdx.x * blockDim.x + threadIdx.x;
    if (e < NE) g_rank[e] = atomicAdd(&g_cnt[dst[e]], 1);
}

__global__ void scan_all_kernel() {  // single-block exclusive scan
    __shared__ int ws[32];
    __shared__ int tshare;
    int t = threadIdx.x, lane = t & 31, wid = t >> 5;
    int carry = 0;
    const int nchunks = (NV + 1023) / 1024;
    for (int c = 0; c < nchunks; c++) {
        int i = c * 1024 + t;
        int x = (i < NV) ? g_cnt[i] : 0;
        int incl = x;
        #pragma unroll
        for (int o = 1; o < 32; o <<= 1) {
            int n = __shfl_up_sync(0xffffffffu, incl, o);
            if (lane >= o) incl += n;
        }
        if (lane == 31) ws[wid] = incl;
        __syncthreads();
        if (t < 32) {
            int v = ws[t];
            int iv = v;
            #pragma unroll
            for (int o = 1; o < 32; o <<= 1) {
                int n = __shfl_up_sync(0xffffffffu, iv, o);
                if (t >= o) iv += n;
            }
            ws[t] = iv - v;
        }
        __syncthreads();
        int excl = ws[wid] + incl - x;
        if (i < NV) g_off[i] = carry + excl;
        if (t == 1023) tshare = excl + x;
        __syncthreads();
        carry += tshare;
        __syncthreads();
    }
    if (t == 0) g_off[NV] = NE;
}

__global__ void zero_cnt_kernel() {  // runs LAST
    int i = blockIdx.x * blockDim.x + threadIdx.x;
    if (i < NV) g_cnt[i] = 0;
}

// ---------------- h = node_feats @ Wn + bn ----------------------------------
struct HSmem {
    __half As[128][72];
    unsigned Wp[2048];
    float bs[64];
};
__global__ void __launch_bounds__(256, 2)
h_kernel(const float* __restrict__ nf, const float* __restrict__ Wn,
         const float* __restrict__ bn) {
    extern __shared__ char smraw[];
    HSmem& sm = *reinterpret_cast<HSmem*>(smraw);
    int tid = threadIdx.x, lane = tid & 31, warp = tid >> 5;
    int gid = lane >> 2, tig = lane & 3, wr = warp * 16;
    packW(Wn, sm.Wp, tid, 256);
    if (tid < 64) sm.bs[tid] = bn[tid];
    int base = blockIdx.x * 128;
    int rows = min(128, NV - base);
    #pragma unroll
    for (int j = 0; j < 8; j++) {
        int f4 = tid + j * 256;
        int r = f4 >> 4, c4 = f4 & 15;
        float4 v = (r < rows) ? ((const float4*)(nf + (size_t)(base + r) * DD))[c4]
                              : make_float4(0.f, 0.f, 0.f, 0.f);
        __half2 h0 = __floats2half2_rn(v.x, v.y);
        __half2 h1 = __floats2half2_rn(v.z, v.w);
        *(uint2*)&sm.As[r][c4 * 4] = make_uint2(*(unsigned*)&h0, *(unsigned*)&h1);
    }
    __syncthreads();
    float acc[8][4];
    #pragma unroll
    for (int i = 0; i < 8; i++)
        #pragma unroll
        for (int j = 0; j < 4; j++) acc[i][j] = 0.f;
    gemm_tile(sm.As, sm.Wp, acc, wr, gid, tig, lane);
    #pragma unroll
    for (int nt = 0; nt < 8; nt++) {
        int c0 = nt * 8 + tig * 2;
        float b0 = sm.bs[c0], b1 = sm.bs[c0 + 1];
        int r0 = wr + gid, r1 = wr + gid + 8;
        if (r0 < rows)
            *(float2*)(g_h + (size_t)(base + r0) * DD + c0) =
                make_float2(acc[nt][0] + b0, acc[nt][1] + b1);
        if (r1 < rows)
            *(float2*)(g_h + (size_t)(base + r1) * DD + c0) =
                make_float2(acc[nt][2] + b0, acc[nt][3] + b1);
    }
}

// ---------------- edge kernel: warp-independent, acc-chained, W2-in-regs ----
struct EdgeSmem {
    __half As[64][72];     // 16 rows per warp (4 warps): ef tile / msg staging
    unsigned Wp1[2048];
    unsigned Wp2[2048];    // staging for the register load
    float b1s[64], b2s[64];
};
__global__ void __launch_bounds__(128, 3)
edge_kernel(const float* __restrict__ ef, const int* __restrict__ src,
            const int* __restrict__ dst, const float* __restrict__ We1,
            const float* __restrict__ be1, const float* __restrict__ We2,
            const float* __restrict__ be2) {
    extern __shared__ char smraw[];
    EdgeSmem& sm = *reinterpret_cast<EdgeSmem*>(smraw);
    const int tid = threadIdx.x, lane = tid & 31, warp = tid >> 5;  // 4 warps
    const int gid = lane >> 2, tig = lane & 3;
    const int wr = warp * 16;               // this warp's first smem row

    packW(We1, sm.Wp1, tid, 128);
    packW(We2, sm.Wp2, tid, 128);
    if (tid < 64) { sm.b1s[tid] = be1[tid]; sm.b2s[tid] = be2[tid]; }
    __syncthreads();

    // W2 B-fragments -> registers (one-time; kills 64 LDS.64 per tile)
    uint2 w2r[32];
    #pragma unroll
    for (int i = 0; i < 32; i++) w2r[i] = ((const uint2*)sm.Wp2)[i * 32 + lane];

    // lane's ldmatrix base address into its warp's 16 rows
    const int row_l = (lane & 7) + ((lane >> 3) & 1) * 8;
    const int col_l = (lane >> 4) * 8;  // halves
    const uint32_t aAddr =
        (uint32_t)__cvta_generic_to_shared(&sm.As[wr + row_l][col_l]);
    // ef-load / scatter addressing: 2 lanes per row, 64B per lane
    const int ldRow = lane >> 1, ldHalf = lane & 1;

    const int gw = blockIdx.x * 4 + warp;       // global warp id
    const int nw = gridDim.x * 4;
    const int numT = NE / 16;                   // 78125 exactly

    for (int t16 = gw; t16 < numT; t16 += nw) {
        const int base = t16 * 16;

        // per-lane metadata (rows 0..15 in lanes 0..15)
        int slotreg = 0, srcreg = 0;
        if (lane < 16) {
            slotreg = g_off[dst[base + lane]] + g_rank[base + lane];
            srcreg  = src[base + lane];
        }

        // load 16x64 ef tile -> fp16 smem (warp-private rows)
        {
            const float4* efp =
                (const float4*)(ef + (size_t)(base + ldRow) * DD) + ldHalf * 8;
            __half* dstRow = &sm.As[wr + ldRow][ldHalf * 32];
            #pragma unroll
            for (int j = 0; j < 8; j++) {
                float4 v = efp[j];
                __half2 h0 = __floats2half2_rn(v.x, v.y);
                __half2 h1 = __floats2half2_rn(v.z, v.w);
                *(uint2*)&dstRow[j * 4] = make_uint2(*(unsigned*)&h0, *(unsigned*)&h1);
            }
        }
        __syncwarp();

        // ---- GEMM1: A via ldmatrix, B via smem fragments ----
        float acc[8][4];
        #pragma unroll
        for (int i = 0; i < 8; i++)
            #pragma unroll
            for (int j = 0; j < 4; j++) acc[i][j] = 0.f;
        #pragma unroll
        for (int ks = 0; ks < 4; ks++) {
            unsigned a0, a1, a2, a3;
            ldsm4(a0, a1, a2, a3, aAddr + ks * 32);
            #pragma unroll
            for (int nt = 0; nt < 8; nt++) {
                uint2 b = ((const uint2*)sm.Wp1)[(ks * 8 + nt) * 32 + lane];
                mma_f16(acc[nt], a0, a1, a2, a3, b.x, b.y);
            }
        }

        // issue h[src] gathers early (fly during conversion + GEMM2)
        int s0 = __shfl_sync(0xffffffffu, srcreg, gid);
        int s1 = __shfl_sync(0xffffffffu, srcreg, gid + 8);
        const float2* h0p = (const float2*)(g_h + (size_t)s0 * DD);
        const float2* h1p = (const float2*)(g_h + (size_t)s1 * DD);
        float2 hv0[8], hv1[8];
        #pragma unroll
        for (int nt = 0; nt < 8; nt++) {
            hv0[nt] = h0p[nt * 4 + tig];
            hv1[nt] = h1p[nt * 4 + tig];
        }

        // ---- acc-chaining: ssp(acc1 + b1) -> GEMM2 A-fragments in regs ----
        // acc[nt] holds rows (gid, gid+8), cols nt*8+tig*2(,+1).
        // GEMM2 A-frag ks: a0=row gid cols ks*16+tig*2 -> acc[2ks];
        //                  a2=row gid cols ks*16+8+tig*2 -> acc[2ks+1]; etc.
        unsigned afr[16];
        #pragma unroll
        for (int ks = 0; ks < 4; ks++) {
            int c0 = ks * 16 + tig * 2;
            int c1 = c0 + 8;
            float b00 = sm.b1s[c0], b01 = sm.b1s[c0 + 1];
            float b10 = sm.b1s[c1], b11 = sm.b1s[c1 + 1];
            __half2 t0 = __floats2half2_rn(sspf(acc[2 * ks][0] + b00),
                                           sspf(acc[2 * ks][1] + b01));
            __half2 t1 = __floats2half2_rn(sspf(acc[2 * ks][2] + b00),
                                           sspf(acc[2 * ks][3] + b01));
            __half2 t2 = __floats2half2_rn(sspf(acc[2 * ks + 1][0] + b10),
                                           sspf(acc[2 * ks + 1][1] + b11));
            __half2 t3 = __floats2half2_rn(sspf(acc[2 * ks + 1][2] + b10),
                                           sspf(acc[2 * ks + 1][3] + b11));
            afr[ks * 4 + 0] = *(unsigned*)&t0;
            afr[ks * 4 + 1] = *(unsigned*)&t1;
            afr[ks * 4 + 2] = *(unsigned*)&t2;
            afr[ks * 4 + 3] = *(unsigned*)&t3;
        }

        // ---- GEMM2: A from registers, B from registers ----
        #pragma unroll
        for (int i = 0; i < 8; i++)
            #pragma unroll
            for (int j = 0; j < 4; j++) acc[i][j] = 0.f;
        #pragma unroll
        for (int ks = 0; ks < 4; ks++) {
            #pragma unroll
            for (int nt = 0; nt < 8; nt++) {
                uint2 b = w2r[ks * 8 + nt];
                mma_f16(acc[nt], afr[ks * 4 + 0], afr[ks * 4 + 1],
                        afr[ks * 4 + 2], afr[ks * 4 + 3], b.x, b.y);
            }
        }

        // msg = ssp(acc2 + b2) * h -> fp16 staging in own rows
        #pragma unroll
        for (int nt = 0; nt < 8; nt++) {
            int c0 = nt * 8 + tig * 2;
            float b0 = sm.b2s[c0], b1 = sm.b2s[c0 + 1];
            float m0 = sspf(acc[nt][0] + b0) * hv0[nt].x;
            float m1 = sspf(acc[nt][1] + b1) * hv0[nt].y;
            float m2 = sspf(acc[nt][2] + b0) * hv1[nt].x;
            float m3 = sspf(acc[nt][3] + b1) * hv1[nt].y;
            *(__half2*)&sm.As[wr + gid    ][c0] = __floats2half2_rn(m0, m1);
            *(__half2*)&sm.As[wr + gid + 8][c0] = __floats2half2_rn(m2, m3);
        }
        __syncwarp();

        // coalesced scatter: 2 lanes per row, 64B each, slot via shuffle
        {
            int slot = __shfl_sync(0xffffffffu, slotreg, ldRow);
            const uint4* sp = (const uint4*)&sm.As[wr + ldRow][ldHalf * 32];
            uint4* dp = (uint4*)(g_msg + (size_t)slot * DD + ldHalf * 32);
            #pragma unroll
            for (int i = 0; i < 4; i++) dp[i] = sp[i];
        }
        __syncwarp();
    }
}

// ---------------- node kernel: segment-sum + ssp(agg@Wc+bc)@Wo+bo -----------
struct NodeSmem {
    float Wc[64][64];
    float Wo[64][64];
    float agg[16][64];
    float bcs[64], bos[64];
};
__global__ void __launch_bounds__(512, 2)
node_kernel(const float* __restrict__ Wc, const float* __restrict__ bc,
            const float* __restrict__ Wo, const float* __restrict__ bo,
            float* __restrict__ out) {
    extern __shared__ char smraw[];
    NodeSmem& sm = *reinterpret_cast<NodeSmem*>(smraw);
    int tid = threadIdx.x, lane = tid & 31, warp = tid >> 5;  // 16 warps
    for (int i = tid; i < 4096; i += 512) ((float*)sm.Wc)[i] = Wc[i];
    for (int i = tid; i < 4096; i += 512) ((float*)sm.Wo)[i] = Wo[i];
    if (tid < 64) { sm.bcs[tid] = bc[tid]; sm.bos[tid] = bo[tid]; }
    __syncthreads();

    int v = blockIdx.x * 16 + warp;  // NV = 3125*16 exactly
    int s0 = g_off[v], s1 = g_off[v + 1];
    float a0 = 0.f, a1 = 0.f;
    const unsigned* mp = (const unsigned*)g_msg;
    #pragma unroll 4
    for (int s = s0; s < s1; s++) {
        unsigned u = mp[(size_t)s * 32 + lane];  // 128B coalesced per warp
        float2 f = __half22float2(*(__half2*)&u);
        a0 += f.x;
        a1 += f.y;
    }
    sm.agg[warp][2 * lane]     = a0;
    sm.agg[warp][2 * lane + 1] = a1;
    __syncwarp();

    float o0 = sm.bcs[2 * lane], o1 = sm.bcs[2 * lane + 1];
    #pragma unroll 8
    for (int k = 0; k < 64; k++) {
        float av = sm.agg[warp][k];
        float2 w = *(const float2*)&sm.Wc[k][2 * lane];
        o0 += av * w.x;
        o1 += av * w.y;
    }
    o0 = sspf(o0);
    o1 = sspf(o1);
    __syncwarp();
    sm.agg[warp][2 * lane]     = o0;
    sm.agg[warp][2 * lane + 1] = o1;
    __syncwarp();

    float r0 = sm.bos[2 * lane], r1 = sm.bos[2 * lane + 1];
    #pragma unroll 8
    for (int k = 0; k < 64; k++) {
        float tv = sm.agg[warp][k];
        float2 w = *(const float2*)&sm.Wo[k][2 * lane];
        r0 += tv * w.x;
        r1 += tv * w.y;
    }
    *(float2*)(out + (size_t)v * DD + 2 * lane) = make_float2(r0, r1);
}

// ---------------- launch ----------------------------------------------------
extern "C" void kernel_launch(void* const* d_in, const int* in_sizes, int n_in,
                              void* d_out, int out_size) {
    const float* nf  = (const float*)d_in[0];
    const float* ef  = (const float*)d_in[1];
    const int*   src = (const int*)d_in[2];
    const int*   dst = (const int*)d_in[3];
    const float* We1 = (const float*)d_in[4];
    const float* be1 = (const float*)d_in[5];
    const float* We2 = (const float*)d_in[6];
    const float* be2 = (const float*)d_in[7];
    const float* Wn  = (const float*)d_in[8];
    const float* bn  = (const float*)d_in[9];
    const float* Wc  = (const float*)d_in[10];
    const float* bc  = (const float*)d_in[11];
    const float* Wo  = (const float*)d_in[12];
    const float* bo  = (const float*)d_in[13];
    float* out = (float*)d_out;

    cudaFuncSetAttribute(edge_kernel, cudaFuncAttributeMaxDynamicSharedMemorySize,
                         (int)sizeof(EdgeSmem));
    cudaFuncSetAttribute(h_kernel, cudaFuncAttributeMaxDynamicSharedMemorySize,
                         (int)sizeof(HSmem));
    cudaFuncSetAttribute(node_kernel, cudaFuncAttributeMaxDynamicSharedMemorySize,
                         (int)sizeof(NodeSmem));

    hist_kernel<<<(NE + 255) / 256, 256>>>(dst);
    scan_all_kernel<<<1, 1024>>>();
    h_kernel<<<(NV + 127) / 128, 256, sizeof(HSmem)>>>(nf, Wn, bn);
    edge_kernel<<<444, 128, sizeof(EdgeSmem)>>>(ef, src, dst, We1, be1, We2, be2);
    node_kernel<<<NV / 16, 512, sizeof(NodeSmem)>>>(Wc, bc, Wo, bo, out);
    zero_cnt_kernel<<<(NV + 1023) / 1024, 1024>>>();
}

// round 11
// speedup vs baseline: 1.1332x; 1.1197x over previous
#include <cuda_runtime.h>
#include <cuda_fp16.h>
#include <cstdint>

#define NV 50000
#define NE 1250000
#define DD 64

// ---------------- scratch (device globals: no runtime allocation allowed) ----
__device__ float  g_h[(size_t)NV * DD];        // node projection h = nf@Wn + bn
__device__ __half g_msg[(size_t)NE * DD];      // messages, dst-sorted (CSR) order
__device__ int    g_rank[NE];                  // rank of edge within its dst bucket
__device__ int    g_cnt[NV];                   // histogram (zero at entry; re-zeroed last)
__device__ int    g_off[NV + 1];               // CSR offsets
__device__ int    g_bsum[64];                  // scan block sums

// ---------------- helpers ---------------------------------------------------
__device__ __forceinline__ float sspf(float x) {
    // shifted softplus via fast-math MUFU: log(1+e^x) - log(2)
    return fmaxf(x, 0.f) + __logf(1.f + __expf(-fabsf(x))) - 0.69314718055994531f;
}

// fp16 mma m16n8k16, fp32 accumulate
__device__ __forceinline__ void mma_f16(float c[4], unsigned a0, unsigned a1,
                                        unsigned a2, unsigned a3,
                                        unsigned b0, unsigned b1) {
    asm("mma.sync.aligned.m16n8k16.row.col.f32.f16.f16.f32 "
        "{%0,%1,%2,%3}, {%4,%5,%6,%7}, {%8,%9}, {%0,%1,%2,%3};"
        : "+f"(c[0]), "+f"(c[1]), "+f"(c[2]), "+f"(c[3])
        : "r"(a0), "r"(a1), "r"(a2), "r"(a3), "r"(b0), "r"(b1));
}

// Pack 64x64 row-major W into per-lane m16n8k16 B-fragment order (fp16).
__device__ __forceinline__ void packW(const float* __restrict__ W, unsigned* Wp,
                                      int tid, int nthr) {
    for (int idx = tid; idx < 2048; idx += nthr) {
        int j    = idx & 1;
        int lane = (idx >> 1) & 31;
        int nt   = (idx >> 6) & 7;
        int ks   = idx >> 9;                  // 0..3
        int g = lane >> 2, t4 = lane & 3;
        int kb = ks * 16 + t4 * 2 + j * 8;
        int n  = nt * 8 + g;
        __half2 v = __floats2half2_rn(W[kb * DD + n], W[(kb + 1) * DD + n]);
        Wp[idx] = *(unsigned*)&v;
    }
}

// [128,64] @ [64,64] per block (A fp16 in smem, W pre-packed fragments).
__device__ __forceinline__ void gemm_tile(const __half (*As)[72],
                                          const unsigned* __restrict__ Wp,
                                          float acc[8][4], int wr, int gid,
                                          int tig, int lane) {
    #pragma unroll
    for (int ks = 0; ks < 4; ks++) {
        int k0 = ks * 16 + tig * 2;
        unsigned a0 = *(const unsigned*)&As[wr + gid    ][k0];
        unsigned a1 = *(const unsigned*)&As[wr + gid + 8][k0];
        unsigned a2 = *(const unsigned*)&As[wr + gid    ][k0 + 8];
        unsigned a3 = *(const unsigned*)&As[wr + gid + 8][k0 + 8];
        #pragma unroll
        for (int nt = 0; nt < 8; nt++) {
            uint2 b = ((const uint2*)Wp)[(ks * 8 + nt) * 32 + lane];
            mma_f16(acc[nt], a0, a1, a2, a3, b.x, b.y);
        }
    }
}

// ---------------- CSR build (3-phase parallel scan) --------------------------
__global__ void hist_kernel(const int* __restrict__ dst) {
    int e = blockIdx.x * blockDim.x + threadIdx.x;
    if (e < NE) g_rank[e] = atomicAdd(&g_cnt[dst[e]], 1);
}
__global__ void scan1_kernel() {
    __shared__ int ws[32];
    int t = threadIdx.x, b = blockIdx.x;
    int i = b * 1024 + t;
    int x = (i < NV) ? g_cnt[i] : 0;
    int incl = x;
    #pragma unroll
    for (int o = 1; o < 32; o <<= 1) {
        int n = __shfl_up_sync(0xffffffffu, incl, o);
        if ((t & 31) >= o) incl += n;
    }
    if ((t & 31) == 31) ws[t >> 5] = incl;
    __syncthreads();
    if (t < 32) {
        int v = ws[t];
        int iv = v;
        #pragma unroll
        for (int o = 1; o < 32; o <<= 1) {
            int n = __shfl_up_sync(0xffffffffu, iv, o);
            if (t >= o) iv += n;
        }
        ws[t] = iv - v;  // exclusive warp prefix
    }
    __syncthreads();
    int excl = ws[t >> 5] + incl - x;
    if (i < NV) g_off[i] = excl;
    if (t == 1023) g_bsum[b] = excl + x;
}
__global__ void scan2_kernel() {
    int run = 0;
    const int nb = (NV + 1023) / 1024;
    for (int b = 0; b < nb; b++) {
        int v = g_bsum[b];
        g_bsum[b] = run;
        run += v;
    }
}
__global__ void scan3_kernel() {
    int t = threadIdx.x, b = blockIdx.x;
    int i = b * 1024 + t;
    if (i < NV) g_off[i] += g_bsum[b];
    if (i == 0) g_off[NV] = NE;
}
__global__ void zero_cnt_kernel() {  // runs LAST
    int i = blockIdx.x * blockDim.x + threadIdx.x;
    if (i < NV) g_cnt[i] = 0;
}

// ---------------- h = node_feats @ Wn + bn ----------------------------------
struct HSmem {
    __half As[128][72];
    unsigned Wp[2048];
    float bs[64];
};
__global__ void __launch_bounds__(256, 2)
h_kernel(const float* __restrict__ nf, const float* __restrict__ Wn,
         const float* __restrict__ bn) {
    extern __shared__ char smraw[];
    HSmem& sm = *reinterpret_cast<HSmem*>(smraw);
    int tid = threadIdx.x, lane = tid & 31, warp = tid >> 5;
    int gid = lane >> 2, tig = lane & 3, wr = warp * 16;
    packW(Wn, sm.Wp, tid, 256);
    if (tid < 64) sm.bs[tid] = bn[tid];
    int base = blockIdx.x * 128;
    int rows = min(128, NV - base);
    #pragma unroll
    for (int j = 0; j < 8; j++) {
        int f4 = tid + j * 256;
        int r = f4 >> 4, c4 = f4 & 15;
        float4 v = (r < rows) ? ((const float4*)(nf + (size_t)(base + r) * DD))[c4]
                              : make_float4(0.f, 0.f, 0.f, 0.f);
        __half2 h0 = __floats2half2_rn(v.x, v.y);
        __half2 h1 = __floats2half2_rn(v.z, v.w);
        *(uint2*)&sm.As[r][c4 * 4] = make_uint2(*(unsigned*)&h0, *(unsigned*)&h1);
    }
    __syncthreads();
    float acc[8][4];
    #pragma unroll
    for (int i = 0; i < 8; i++)
        #pragma unroll
        for (int j = 0; j < 4; j++) acc[i][j] = 0.f;
    gemm_tile(sm.As, sm.Wp, acc, wr, gid, tig, lane);
    #pragma unroll
    for (int nt = 0; nt < 8; nt++) {
        int c0 = nt * 8 + tig * 2;
        float b0 = sm.bs[c0], b1 = sm.bs[c0 + 1];
        int r0 = wr + gid, r1 = wr + gid + 8;
        if (r0 < rows)
            *(float2*)(g_h + (size_t)(base + r0) * DD + c0) =
                make_float2(acc[nt][0] + b0, acc[nt][1] + b1);
        if (r1 < rows)
            *(float2*)(g_h + (size_t)(base + r1) * DD + c0) =
                make_float2(acc[nt][2] + b0, acc[nt][3] + b1);
    }
}

// ---------------- edge kernel (R7-best): block tiles, reg h-gather ----------
struct EdgeSmem {
    __half As[128][72];    // fp16 edge tile / intermediate / fp16 msg staging
    unsigned Wp1[2048];
    unsigned Wp2[2048];
    float b1s[64], b2s[64];
    int slotS[128];
};
__global__ void __launch_bounds__(256, 3)
edge_kernel(const float* __restrict__ ef, const int* __restrict__ src,
            const int* __restrict__ dst, const float* __restrict__ We1,
            const float* __restrict__ be1, const float* __restrict__ We2,
            const float* __restrict__ be2) {
    extern __shared__ char smraw[];
    EdgeSmem& sm = *reinterpret_cast<EdgeSmem*>(smraw);
    const int tid = threadIdx.x, lane = tid & 31, warp = tid >> 5;
    const int gid = lane >> 2, tig = lane & 3, wr = warp * 16;
    const int r0 = wr + gid, r1 = r0 + 8;  // the two rows this thread owns

    packW(We1, sm.Wp1, tid, 256);
    packW(We2, sm.Wp2, tid, 256);
    if (tid < 64) { sm.b1s[tid] = be1[tid]; sm.b2s[tid] = be2[tid]; }

    const int numTiles = (NE + 127) / 128;
    for (int tile = blockIdx.x; tile < numTiles; tile += gridDim.x) {
        const int base = tile * 128;
        const int rows = min(128, NE - base);
        __syncthreads();  // prev-iter readers done; Wp ready (first iter)

        if (tid < 128 && tid < rows)
            sm.slotS[tid] = g_off[dst[base + tid]] + g_rank[base + tid];

        #pragma unroll
        for (int j = 0; j < 8; j++) {
            int f4 = tid + j * 256;
            int r = f4 >> 4, c4 = f4 & 15;
            float4 v = (r < rows)
                           ? ((const float4*)(ef + (size_t)(base + r) * DD))[c4]
                           : make_float4(0.f, 0.f, 0.f, 0.f);
            __half2 h0 = __floats2half2_rn(v.x, v.y);
            __half2 h1 = __floats2half2_rn(v.z, v.w);
            *(uint2*)&sm.As[r][c4 * 4] = make_uint2(*(unsigned*)&h0, *(unsigned*)&h1);
        }
        __syncthreads();

        float acc[8][4];
        #pragma unroll
        for (int i = 0; i < 8; i++)
            #pragma unroll
            for (int j = 0; j < 4; j++) acc[i][j] = 0.f;
        gemm_tile(sm.As, sm.Wp1, acc, wr, gid, tig, lane);
        __syncthreads();

        // ssp(x + b1) -> back into As (fp16)
        #pragma unroll
        for (int nt = 0; nt < 8; nt++) {
            int c0 = nt * 8 + tig * 2;
            float b0 = sm.b1s[c0], b1 = sm.b1s[c0 + 1];
            __half2 v0 = __floats2half2_rn(sspf(acc[nt][0] + b0), sspf(acc[nt][1] + b1));
            __half2 v1 = __floats2half2_rn(sspf(acc[nt][2] + b0), sspf(acc[nt][3] + b1));
            *(__half2*)&sm.As[wr + gid    ][c0] = v0;
            *(__half2*)&sm.As[wr + gid + 8][c0] = v1;
        }
        __syncthreads();

        // h[src] gathers for this thread's rows (fly during gemm2 below)
        int s0 = (r0 < rows) ? src[base + r0] : 0;
        int s1 = (r1 < rows) ? src[base + r1] : 0;
        const float2* h0p = (const float2*)(g_h + (size_t)s0 * DD);
        const float2* h1p = (const float2*)(g_h + (size_t)s1 * DD);
        float2 hv0[8], hv1[8];
        #pragma unroll
        for (int nt = 0; nt < 8; nt++) {
            hv0[nt] = h0p[nt * 4 + tig];
            hv1[nt] = h1p[nt * 4 + tig];
        }

        #pragma unroll
        for (int i = 0; i < 8; i++)
            #pragma unroll
            for (int j = 0; j < 4; j++) acc[i][j] = 0.f;
        gemm_tile(sm.As, sm.Wp2, acc, wr, gid, tig, lane);
        __syncthreads();  // all warps done reading As before staging msg in it

        // f = ssp(x + b2); msg = f * h; stage as fp16 (reuse As, stride 72)
        __half* MsgS = (__half*)&sm.As[0][0];
        #pragma unroll
        for (int nt = 0; nt < 8; nt++) {
            int c0 = nt * 8 + tig * 2;
            float b0 = sm.b2s[c0], b1 = sm.b2s[c0 + 1];
            float m0 = sspf(acc[nt][0] + b0) * hv0[nt].x;
            float m1 = sspf(acc[nt][1] + b1) * hv0[nt].y;
            float m2 = sspf(acc[nt][2] + b0) * hv1[nt].x;
            float m3 = sspf(acc[nt][3] + b1) * hv1[nt].y;
            *(__half2*)&MsgS[r0 * 72 + c0] = __floats2half2_rn(m0, m1);
            *(__half2*)&MsgS[r1 * 72 + c0] = __floats2half2_rn(m2, m3);
        }
        __syncthreads();

        // scatter whole 128B rows to their CSR slot (coalesced 64B per thread)
        {
            int r = tid >> 1, part = tid & 1;
            if (r < rows) {
                int slot = sm.slotS[r];
                const uint4* sp = (const uint4*)&MsgS[r * 72 + part * 32];
                uint4* dp = (uint4*)(g_msg + (size_t)slot * DD + part * 32);
                #pragma unroll
                for (int i = 0; i < 4; i++) dp[i] = sp[i];
            }
        }
    }
}

// ---------------- node kernel: 2-rows/iter segment-sum + fused MLP ----------
struct NodeSmem {
    float Wc[64][64];
    float Wo[64][64];
    float agg[16][64];
    float bcs[64], bos[64];
};
__global__ void __launch_bounds__(512, 2)
node_kernel(const float* __restrict__ Wc, const float* __restrict__ bc,
            const float* __restrict__ Wo, const float* __restrict__ bo,
            float* __restrict__ out) {
    extern __shared__ char smraw[];
    NodeSmem& sm = *reinterpret_cast<NodeSmem*>(smraw);
    int tid = threadIdx.x, lane = tid & 31, warp = tid >> 5;  // 16 warps
    for (int i = tid; i < 4096; i += 512) ((float*)sm.Wc)[i] = Wc[i];
    for (int i = tid; i < 4096; i += 512) ((float*)sm.Wo)[i] = Wo[i];
    if (tid < 64) { sm.bcs[tid] = bc[tid]; sm.bos[tid] = bo[tid]; }
    __syncthreads();

    int v = blockIdx.x * 16 + warp;  // NV = 3125*16 exactly
    int s0 = g_off[v], s1 = g_off[v + 1];
    // lane reads uint2 (4 halves) covering 2 rows per iteration:
    //   row = s + (lane>>4), cols (lane&15)*4 .. +3
    const int rsel = lane >> 4, c4 = (lane & 15) * 4;
    float a0 = 0.f, a1 = 0.f, a2 = 0.f, a3 = 0.f;
    const uint2* mp =
        (const uint2*)(g_msg) /* 8B units */;
    #pragma unroll 4
    for (int s = s0; s < s1; s += 2) {
        int row = s + rsel;
        if (row < s1) {
            uint2 u = *(const uint2*)(g_msg + (size_t)row * DD + c4);
            float2 f0 = __half22float2(*(__half2*)&u.x);
            float2 f1 = __half22float2(*(__half2*)&u.y);
            a0 += f0.x; a1 += f0.y; a2 += f1.x; a3 += f1.y;
        }
    }
    (void)mp;
    // combine the two row-halves (lanes l and l^16 hold same cols)
    a0 += __shfl_xor_sync(0xffffffffu, a0, 16);
    a1 += __shfl_xor_sync(0xffffffffu, a1, 16);
    a2 += __shfl_xor_sync(0xffffffffu, a2, 16);
    a3 += __shfl_xor_sync(0xffffffffu, a3, 16);
    if (lane < 16)
        *(float4*)&sm.agg[warp][c4] = make_float4(a0, a1, a2, a3);
    __syncwarp();

    float o0 = sm.bcs[2 * lane], o1 = sm.bcs[2 * lane + 1];
    #pragma unroll 8
    for (int k = 0; k < 64; k++) {
        float av = sm.agg[warp][k];
        float2 w = *(const float2*)&sm.Wc[k][2 * lane];
        o0 += av * w.x;
        o1 += av * w.y;
    }
    o0 = sspf(o0);
    o1 = sspf(o1);
    __syncwarp();
    sm.agg[warp][2 * lane]     = o0;
    sm.agg[warp][2 * lane + 1] = o1;
    __syncwarp();

    float r0 = sm.bos[2 * lane], r1 = sm.bos[2 * lane + 1];
    #pragma unroll 8
    for (int k = 0; k < 64; k++) {
        float tv = sm.agg[warp][k];
        float2 w = *(const float2*)&sm.Wo[k][2 * lane];
        r0 += tv * w.x;
        r1 += tv * w.y;
    }
    *(float2*)(out + (size_t)v * DD + 2 * lane) = make_float2(r0, r1);
}

// ---------------- launch ----------------------------------------------------
extern "C" void kernel_launch(void* const* d_in, const int* in_sizes, int n_in,
                              void* d_out, int out_size) {
    const float* nf  = (const float*)d_in[0];
    const float* ef  = (const float*)d_in[1];
    const int*   src = (const int*)d_in[2];
    const int*   dst = (const int*)d_in[3];
    const float* We1 = (const float*)d_in[4];
    const float* be1 = (const float*)d_in[5];
    const float* We2 = (const float*)d_in[6];
    const float* be2 = (const float*)d_in[7];
    const float* Wn  = (const float*)d_in[8];
    const float* bn  = (const float*)d_in[9];
    const float* Wc  = (const float*)d_in[10];
    const float* bc  = (const float*)d_in[11];
    const float* Wo  = (const float*)d_in[12];
    const float* bo  = (const float*)d_in[13];
    float* out = (float*)d_out;

    cudaFuncSetAttribute(edge_kernel, cudaFuncAttributeMaxDynamicSharedMemorySize,
                         (int)sizeof(EdgeSmem));
    cudaFuncSetAttribute(h_kernel, cudaFuncAttributeMaxDynamicSharedMemorySize,
                         (int)sizeof(HSmem));
    cudaFuncSetAttribute(node_kernel, cudaFuncAttributeMaxDynamicSharedMemorySize,
                         (int)sizeof(NodeSmem));

    const int scanBlocks = (NV + 1023) / 1024;  // 49
    // g_cnt is zero on entry (.bss on call 1; trailing zero_cnt re-establishes)
    hist_kernel<<<(NE + 255) / 256, 256>>>(dst);
    scan1_kernel<<<scanBlocks, 1024>>>();
    scan2_kernel<<<1, 1>>>();
    scan3_kernel<<<scanBlocks, 1024>>>();
    h_kernel<<<(NV + 127) / 128, 256, sizeof(HSmem)>>>(nf, Wn, bn);
    edge_kernel<<<444, 256, sizeof(EdgeSmem)>>>(ef, src, dst, We1, be1, We2, be2);
    node_kernel<<<NV / 16, 512, sizeof(NodeSmem)>>>(Wc, bc, Wo, bo, out);
    zero_cnt_kernel<<<(NV + 1023) / 1024, 1024>>>();
}

// round 12
// speedup vs baseline: 1.1566x; 1.0207x over previous
#include <cuda_runtime.h>
#include <cuda_fp16.h>
#include <cstdint>

#define NV 50000
#define NE 1250000
#define DD 64

// ---------------- scratch (device globals: no runtime allocation allowed) ----
__device__ __half g_h[(size_t)NV * DD];        // node projection h = nf@Wn + bn (fp16)
__device__ __half g_msg[(size_t)NE * DD];      // messages, dst-sorted (CSR) order
__device__ int    g_rank[NE];                  // rank of edge within its dst bucket
__device__ int    g_cnt[NV];                   // histogram (zero at entry; cleared in scan1)
__device__ int    g_off[NV + 1];               // CSR offsets
__device__ int    g_bsum[64];                  // scan block sums

// ---------------- helpers ---------------------------------------------------
__device__ __forceinline__ float sspf(float x) {
    // shifted softplus via fast-math MUFU: log(1+e^x) - log(2)
    return fmaxf(x, 0.f) + __logf(1.f + __expf(-fabsf(x))) - 0.69314718055994531f;
}

// fp16 mma m16n8k16, fp32 accumulate
__device__ __forceinline__ void mma_f16(float c[4], unsigned a0, unsigned a1,
                                        unsigned a2, unsigned a3,
                                        unsigned b0, unsigned b1) {
    asm("mma.sync.aligned.m16n8k16.row.col.f32.f16.f16.f32 "
        "{%0,%1,%2,%3}, {%4,%5,%6,%7}, {%8,%9}, {%0,%1,%2,%3};"
        : "+f"(c[0]), "+f"(c[1]), "+f"(c[2]), "+f"(c[3])
        : "r"(a0), "r"(a1), "r"(a2), "r"(a3), "r"(b0), "r"(b1));
}

// Pack 64x64 row-major W into per-lane m16n8k16 B-fragment order (fp16).
__device__ __forceinline__ void packW(const float* __restrict__ W, unsigned* Wp,
                                      int tid, int nthr) {
    for (int idx = tid; idx < 2048; idx += nthr) {
        int j    = idx & 1;
        int lane = (idx >> 1) & 31;
        int nt   = (idx >> 6) & 7;
        int ks   = idx >> 9;                  // 0..3
        int g = lane >> 2, t4 = lane & 3;
        int kb = ks * 16 + t4 * 2 + j * 8;
        int n  = nt * 8 + g;
        __half2 v = __floats2half2_rn(W[kb * DD + n], W[(kb + 1) * DD + n]);
        Wp[idx] = *(unsigned*)&v;
    }
}

// [128,64] @ [64,64] per block (A fp16 in smem, W pre-packed fragments).
__device__ __forceinline__ void gemm_tile(const __half (*As)[72],
                                          const unsigned* __restrict__ Wp,
                                          float acc[8][4], int wr, int gid,
                                          int tig, int lane) {
    #pragma unroll
    for (int ks = 0; ks < 4; ks++) {
        int k0 = ks * 16 + tig * 2;
        unsigned a0 = *(const unsigned*)&As[wr + gid    ][k0];
        unsigned a1 = *(const unsigned*)&As[wr + gid + 8][k0];
        unsigned a2 = *(const unsigned*)&As[wr + gid    ][k0 + 8];
        unsigned a3 = *(const unsigned*)&As[wr + gid + 8][k0 + 8];
        #pragma unroll
        for (int nt = 0; nt < 8; nt++) {
            uint2 b = ((const uint2*)Wp)[(ks * 8 + nt) * 32 + lane];
            mma_f16(acc[nt], a0, a1, a2, a3, b.x, b.y);
        }
    }
}

// ---------------- CSR build (3-phase parallel scan) --------------------------
__global__ void hist_kernel(const int* __restrict__ dst) {
    int e = blockIdx.x * blockDim.x + threadIdx.x;
    if (e < NE) g_rank[e] = atomicAdd(&g_cnt[dst[e]], 1);
}
__global__ void scan1_kernel() {
    __shared__ int ws[32];
    int t = threadIdx.x, b = blockIdx.x;
    int i = b * 1024 + t;
    int x = 0;
    if (i < NV) {
        x = g_cnt[i];
        g_cnt[i] = 0;  // re-establish zero invariant for the next replay
    }
    int incl = x;
    #pragma unroll
    for (int o = 1; o < 32; o <<= 1) {
        int n = __shfl_up_sync(0xffffffffu, incl, o);
        if ((t & 31) >= o) incl += n;
    }
    if ((t & 31) == 31) ws[t >> 5] = incl;
    __syncthreads();
    if (t < 32) {
        int v = ws[t];
        int iv = v;
        #pragma unroll
        for (int o = 1; o < 32; o <<= 1) {
            int n = __shfl_up_sync(0xffffffffu, iv, o);
            if (t >= o) iv += n;
        }
        ws[t] = iv - v;  // exclusive warp prefix
    }
    __syncthreads();
    int excl = ws[t >> 5] + incl - x;
    if (i < NV) g_off[i] = excl;
    if (t == 1023) g_bsum[b] = excl + x;
}
__global__ void scan2_kernel() {
    int run = 0;
    const int nb = (NV + 1023) / 1024;
    for (int b = 0; b < nb; b++) {
        int v = g_bsum[b];
        g_bsum[b] = run;
        run += v;
    }
}
__global__ void scan3_kernel() {
    int t = threadIdx.x, b = blockIdx.x;
    int i = b * 1024 + t;
    if (i < NV) g_off[i] += g_bsum[b];
    if (i == 0) g_off[NV] = NE;
}

// ---------------- h = node_feats @ Wn + bn (fp16 output) ---------------------
struct HSmem {
    __half As[128][72];
    unsigned Wp[2048];
    float bs[64];
};
__global__ void __launch_bounds__(256, 2)
h_kernel(const float* __restrict__ nf, const float* __restrict__ Wn,
         const float* __restrict__ bn) {
    extern __shared__ char smraw[];
    HSmem& sm = *reinterpret_cast<HSmem*>(smraw);
    int tid = threadIdx.x, lane = tid & 31, warp = tid >> 5;
    int gid = lane >> 2, tig = lane & 3, wr = warp * 16;
    packW(Wn, sm.Wp, tid, 256);
    if (tid < 64) sm.bs[tid] = bn[tid];
    int base = blockIdx.x * 128;
    int rows = min(128, NV - base);
    #pragma unroll
    for (int j = 0; j < 8; j++) {
        int f4 = tid + j * 256;
        int r = f4 >> 4, c4 = f4 & 15;
        float4 v = (r < rows) ? ((const float4*)(nf + (size_t)(base + r) * DD))[c4]
                              : make_float4(0.f, 0.f, 0.f, 0.f);
        __half2 h0 = __floats2half2_rn(v.x, v.y);
        __half2 h1 = __floats2half2_rn(v.z, v.w);
        *(uint2*)&sm.As[r][c4 * 4] = make_uint2(*(unsigned*)&h0, *(unsigned*)&h1);
    }
    __syncthreads();
    float acc[8][4];
    #pragma unroll
    for (int i = 0; i < 8; i++)
        #pragma unroll
        for (int j = 0; j < 4; j++) acc[i][j] = 0.f;
    gemm_tile(sm.As, sm.Wp, acc, wr, gid, tig, lane);
    #pragma unroll
    for (int nt = 0; nt < 8; nt++) {
        int c0 = nt * 8 + tig * 2;
        float b0 = sm.bs[c0], b1 = sm.bs[c0 + 1];
        int r0 = wr + gid, r1 = wr + gid + 8;
        if (r0 < rows)
            *(__half2*)(g_h + (size_t)(base + r0) * DD + c0) =
                __floats2half2_rn(acc[nt][0] + b0, acc[nt][1] + b1);
        if (r1 < rows)
            *(__half2*)(g_h + (size_t)(base + r1) * DD + c0) =
                __floats2half2_rn(acc[nt][2] + b0, acc[nt][3] + b1);
    }
}

// ---------------- edge kernel: block tiles, fp16 h-gather --------------------
struct EdgeSmem {
    __half As[128][72];    // fp16 edge tile / intermediate / fp16 msg staging
    unsigned Wp1[2048];
    unsigned Wp2[2048];
    float b1s[64], b2s[64];
    int slotS[128];
};
__global__ void __launch_bounds__(256, 3)
edge_kernel(const float* __restrict__ ef, const int* __restrict__ src,
            const int* __restrict__ dst, const float* __restrict__ We1,
            const float* __restrict__ be1, const float* __restrict__ We2,
            const float* __restrict__ be2) {
    extern __shared__ char smraw[];
    EdgeSmem& sm = *reinterpret_cast<EdgeSmem*>(smraw);
    const int tid = threadIdx.x, lane = tid & 31, warp = tid >> 5;
    const int gid = lane >> 2, tig = lane & 3, wr = warp * 16;
    const int r0 = wr + gid, r1 = r0 + 8;  // the two rows this thread owns

    packW(We1, sm.Wp1, tid, 256);
    packW(We2, sm.Wp2, tid, 256);
    if (tid < 64) { sm.b1s[tid] = be1[tid]; sm.b2s[tid] = be2[tid]; }

    const int numTiles = (NE + 127) / 128;
    for (int tile = blockIdx.x; tile < numTiles; tile += gridDim.x) {
        const int base = tile * 128;
        const int rows = min(128, NE - base);
        __syncthreads();  // prev-iter readers done; Wp ready (first iter)

        if (tid < 128 && tid < rows)
            sm.slotS[tid] = g_off[dst[base + tid]] + g_rank[base + tid];

        #pragma unroll
        for (int j = 0; j < 8; j++) {
            int f4 = tid + j * 256;
            int r = f4 >> 4, c4 = f4 & 15;
            float4 v = (r < rows)
                           ? ((const float4*)(ef + (size_t)(base + r) * DD))[c4]
                           : make_float4(0.f, 0.f, 0.f, 0.f);
            __half2 h0 = __floats2half2_rn(v.x, v.y);
            __half2 h1 = __floats2half2_rn(v.z, v.w);
            *(uint2*)&sm.As[r][c4 * 4] = make_uint2(*(unsigned*)&h0, *(unsigned*)&h1);
        }
        __syncthreads();

        float acc[8][4];
        #pragma unroll
        for (int i = 0; i < 8; i++)
            #pragma unroll
            for (int j = 0; j < 4; j++) acc[i][j] = 0.f;
        gemm_tile(sm.As, sm.Wp1, acc, wr, gid, tig, lane);
        __syncthreads();

        // ssp(x + b1) -> back into As (fp16)
        #pragma unroll
        for (int nt = 0; nt < 8; nt++) {
            int c0 = nt * 8 + tig * 2;
            float b0 = sm.b1s[c0], b1 = sm.b1s[c0 + 1];
            __half2 v0 = __floats2half2_rn(sspf(acc[nt][0] + b0), sspf(acc[nt][1] + b1));
            __half2 v1 = __floats2half2_rn(sspf(acc[nt][2] + b0), sspf(acc[nt][3] + b1));
            *(__half2*)&sm.As[wr + gid    ][c0] = v0;
            *(__half2*)&sm.As[wr + gid + 8][c0] = v1;
        }
        __syncthreads();

        // fp16 h[src] gathers for this thread's rows (fly during gemm2 below)
        int s0 = (r0 < rows) ? src[base + r0] : 0;
        int s1 = (r1 < rows) ? src[base + r1] : 0;
        const __half2* h0p = (const __half2*)(g_h + (size_t)s0 * DD);
        const __half2* h1p = (const __half2*)(g_h + (size_t)s1 * DD);
        __half2 hv0[8], hv1[8];
        #pragma unroll
        for (int nt = 0; nt < 8; nt++) {
            hv0[nt] = h0p[nt * 4 + tig];
            hv1[nt] = h1p[nt * 4 + tig];
        }

        #pragma unroll
        for (int i = 0; i < 8; i++)
            #pragma unroll
            for (int j = 0; j < 4; j++) acc[i][j] = 0.f;
        gemm_tile(sm.As, sm.Wp2, acc, wr, gid, tig, lane);
        __syncthreads();  // all warps done reading As before staging msg in it

        // f = ssp(x + b2); msg = f * h; stage as fp16 (reuse As, stride 72)
        __half* MsgS = (__half*)&sm.As[0][0];
        #pragma unroll
        for (int nt = 0; nt < 8; nt++) {
            int c0 = nt * 8 + tig * 2;
            float b0 = sm.b2s[c0], b1 = sm.b2s[c0 + 1];
            float2 h0f = __half22float2(hv0[nt]);
            float2 h1f = __half22float2(hv1[nt]);
            float m0 = sspf(acc[nt][0] + b0) * h0f.x;
            float m1 = sspf(acc[nt][1] + b1) * h0f.y;
            float m2 = sspf(acc[nt][2] + b0) * h1f.x;
            float m3 = sspf(acc[nt][3] + b1) * h1f.y;
            *(__half2*)&MsgS[r0 * 72 + c0] = __floats2half2_rn(m0, m1);
            *(__half2*)&MsgS[r1 * 72 + c0] = __floats2half2_rn(m2, m3);
        }
        __syncthreads();

        // scatter whole 128B rows to their CSR slot (coalesced 64B per thread)
        {
            int r = tid >> 1, part = tid & 1;
            if (r < rows) {
                int slot = sm.slotS[r];
                const uint4* sp = (const uint4*)&MsgS[r * 72 + part * 32];
                uint4* dp = (uint4*)(g_msg + (size_t)slot * DD + part * 32);
                #pragma unroll
                for (int i = 0; i < 4; i++) dp[i] = sp[i];
            }
        }
    }
}

// ---------------- node kernel: 2-rows/iter segment-sum + fused MLP ----------
struct NodeSmem {
    float Wc[64][64];
    float Wo[64][64];
    float agg[16][64];
    float bcs[64], bos[64];
};
__global__ void __launch_bounds__(512, 2)
node_kernel(const float* __restrict__ Wc, const float* __restrict__ bc,
            const float* __restrict__ Wo, const float* __restrict__ bo,
            float* __restrict__ out) {
    extern __shared__ char smraw[];
    NodeSmem& sm = *reinterpret_cast<NodeSmem*>(smraw);
    int tid = threadIdx.x, lane = tid & 31, warp = tid >> 5;  // 16 warps
    for (int i = tid; i < 4096; i += 512) ((float*)sm.Wc)[i] = Wc[i];
    for (int i = tid; i < 4096; i += 512) ((float*)sm.Wo)[i] = Wo[i];
    if (tid < 64) { sm.bcs[tid] = bc[tid]; sm.bos[tid] = bo[tid]; }
    __syncthreads();

    int v = blockIdx.x * 16 + warp;  // NV = 3125*16 exactly
    int s0 = g_off[v], s1 = g_off[v + 1];
    // lane reads uint2 (4 halves) covering 2 rows per iteration
    const int rsel = lane >> 4, c4 = (lane & 15) * 4;
    float a0 = 0.f, a1 = 0.f, a2 = 0.f, a3 = 0.f;
    #pragma unroll 4
    for (int s = s0; s < s1; s += 2) {
        int row = s + rsel;
        if (row < s1) {
            uint2 u = *(const uint2*)(g_msg + (size_t)row * DD + c4);
            float2 f0 = __half22float2(*(__half2*)&u.x);
            float2 f1 = __half22float2(*(__half2*)&u.y);
            a0 += f0.x; a1 += f0.y; a2 += f1.x; a3 += f1.y;
        }
    }
    // combine the two row-halves (lanes l and l^16 hold same cols)
    a0 += __shfl_xor_sync(0xffffffffu, a0, 16);
    a1 += __shfl_xor_sync(0xffffffffu, a1, 16);
    a2 += __shfl_xor_sync(0xffffffffu, a2, 16);
    a3 += __shfl_xor_sync(0xffffffffu, a3, 16);
    if (lane < 16)
        *(float4*)&sm.agg[warp][c4] = make_float4(a0, a1, a2, a3);
    __syncwarp();

    float o0 = sm.bcs[2 * lane], o1 = sm.bcs[2 * lane + 1];
    #pragma unroll 8
    for (int k = 0; k < 64; k++) {
        float av = sm.agg[warp][k];
        float2 w = *(const float2*)&sm.Wc[k][2 * lane];
        o0 += av * w.x;
        o1 += av * w.y;
    }
    o0 = sspf(o0);
    o1 = sspf(o1);
    __syncwarp();
    sm.agg[warp][2 * lane]     = o0;
    sm.agg[warp][2 * lane + 1] = o1;
    __syncwarp();

    float r0 = sm.bos[2 * lane], r1 = sm.bos[2 * lane + 1];
    #pragma unroll 8
    for (int k = 0; k < 64; k++) {
        float tv = sm.agg[warp][k];
        float2 w = *(const float2*)&sm.Wo[k][2 * lane];
        r0 += tv * w.x;
        r1 += tv * w.y;
    }
    *(float2*)(out + (size_t)v * DD + 2 * lane) = make_float2(r0, r1);
}

// ---------------- launch ----------------------------------------------------
extern "C" void kernel_launch(void* const* d_in, const int* in_sizes, int n_in,
                              void* d_out, int out_size) {
    const float* nf  = (const float*)d_in[0];
    const float* ef  = (const float*)d_in[1];
    const int*   src = (const int*)d_in[2];
    const int*   dst = (const int*)d_in[3];
    const float* We1 = (const float*)d_in[4];
    const float* be1 = (const float*)d_in[5];
    const float* We2 = (const float*)d_in[6];
    const float* be2 = (const float*)d_in[7];
    const float* Wn  = (const float*)d_in[8];
    const float* bn  = (const float*)d_in[9];
    const float* Wc  = (const float*)d_in[10];
    const float* bc  = (const float*)d_in[11];
    const float* Wo  = (const float*)d_in[12];
    const float* bo  = (const float*)d_in[13];
    float* out = (float*)d_out;

    cudaFuncSetAttribute(edge_kernel, cudaFuncAttributeMaxDynamicSharedMemorySize,
                         (int)sizeof(EdgeSmem));
    cudaFuncSetAttribute(h_kernel, cudaFuncAttributeMaxDynamicSharedMemorySize,
                         (int)sizeof(HSmem));
    cudaFuncSetAttribute(node_kernel, cudaFuncAttributeMaxDynamicSharedMemorySize,
                         (int)sizeof(NodeSmem));

    const int scanBlocks = (NV + 1023) / 1024;  // 49
    // g_cnt is zero on entry (.bss on call 1; scan1 clears it for later replays)
    hist_kernel<<<(NE + 255) / 256, 256>>>(dst);
    scan1_kernel<<<scanBlocks, 1024>>>();
    scan2_kernel<<<1, 1>>>();
    scan3_kernel<<<scanBlocks, 1024>>>();
    h_kernel<<<(NV + 127) / 128, 256, sizeof(HSmem)>>>(nf, Wn, bn);
    edge_kernel<<<444, 256, sizeof(EdgeSmem)>>>(ef, src, dst, We1, be1, We2, be2);
    node_kernel<<<NV / 16, 512, sizeof(NodeSmem)>>>(Wc, bc, Wo, bo, out);
}